// round 7
// baseline (speedup 1.0000x reference)
#include <cuda_runtime.h>
#include <cuda_bf16.h>

#define BB 64
#define NN 2048
#define DD 1024
#define SPLIT 32
#define ROWS_BLK (NN / SPLIT)   // 64 rows per block
#define ROWS_W 8                // rows per warp
#define SBUF 3                  // per-warp ring depth
#define ESPLIT 8

#define SMEM_K1 (8 * SBUF * DD * 4)   // 8 warps * 3 slots * 4KB = 98304 B

// Scratch (static device globals; no allocation)
__device__ float g_scores[BB * NN];
__device__ float g_part_m[BB * SPLIT];
__device__ float g_part_l[BB * SPLIT];
__device__ float g_part_mix[BB * SPLIT * DD];    // 8 MB
__device__ float g_comb[BB * 2 * DD];            // [mix | output]
__device__ float g_out_part[BB * DD * ESPLIT];   // es-contiguous, 2 MB
__device__ int   g_ctr_b[BB];                    // zero-init; self-resetting
__device__ int   g_ctr_dt[16];                   // zero-init; self-resetting

__device__ __forceinline__ unsigned smem_u32(const void* p) {
    return (unsigned)__cvta_generic_to_shared(p);
}

// One 4KB row: lane i copies 16B chunks i, 32+i, ... (self-consistent:
// each lane later reads exactly the chunks it issued).
__device__ __forceinline__ void issue_row(float* dst, const float* src,
                                          int lane) {
#pragma unroll
    for (int c = 0; c < 8; c++) {
        const int f = (c * 32 + lane) * 4;   // float index
        unsigned sa = smem_u32(dst + f);
        asm volatile("cp.async.cg.shared.global [%0], [%1], 16;\n"
                     :: "r"(sa), "l"(src + f));
    }
}

// ---------------------------------------------------------------------------
// Kernel 1: per-warp cp.async pipelines + fused split-combine epilogue.
// grid (SPLIT, BB), 256 threads. Warp w owns rows [w*8, w*8+8), private
// 3-slot ring, fully unrolled. Last block per batch b (atomic counter)
// performs the former k2: M/L combine, mix, comb build, attn write.
// ---------------------------------------------------------------------------
__global__ __launch_bounds__(256, 2)
void k1_scores_mix(const float* __restrict__ output,
                   const float* __restrict__ context,
                   float* __restrict__ attn_out) {
    extern __shared__ float smem[];          // 8 * SBUF * DD floats
    __shared__ float sm[8], sl[8];
    __shared__ int is_last;

    const int split = blockIdx.x;
    const int b     = blockIdx.y;
    const int tid   = threadIdx.x;
    const int w     = tid >> 5;
    const int lane  = tid & 31;

    const float* q   = output + (size_t)b * DD;
    const float* ctx = context + (size_t)b * NN * DD
                               + (size_t)(split * ROWS_BLK + w * ROWS_W) * DD;
    float* ring = smem + w * (SBUF * DD);

    float4 qv[8];
#pragma unroll
    for (int j = 0; j < 8; j++)
        qv[j] = *(const float4*)(q + j * 128 + lane * 4);

    float acc[32];
#pragma unroll
    for (int k = 0; k < 32; k++) acc[k] = 0.f;
    float m = -1e30f, l = 0.f;

    // Prologue: rows 0,1 in flight
#pragma unroll
    for (int ps = 0; ps < SBUF - 1; ps++) {
        issue_row(ring + ps * DD, ctx + (size_t)ps * DD, lane);
        asm volatile("cp.async.commit_group;\n");
    }

#pragma unroll
    for (int r = 0; r < ROWS_W; r++) {
        // Issue prefetch BEFORE waiting: steady state keeps 2-3 rows in
        // flight per warp (wait_group 2 still guarantees row r landed,
        // since exactly one group is committed per iteration).
        if (r + SBUF - 1 < ROWS_W)
            issue_row(ring + ((r + SBUF - 1) % SBUF) * DD,
                      ctx + (size_t)(r + SBUF - 1) * DD, lane);
        asm volatile("cp.async.commit_group;\n");
        asm volatile("cp.async.wait_group 2;\n");
        __syncwarp();

        const float* row = ring + (r % SBUF) * DD;
        float4 cv[8];
#pragma unroll
        for (int j = 0; j < 8; j++)
            cv[j] = *(const float4*)(row + j * 128 + lane * 4);

        float s0 = 0.f, s1 = 0.f, s2 = 0.f, s3 = 0.f;
#pragma unroll
        for (int j = 0; j < 8; j++) {
            s0 = fmaf(qv[j].x, cv[j].x, s0);
            s1 = fmaf(qv[j].y, cv[j].y, s1);
            s2 = fmaf(qv[j].z, cv[j].z, s2);
            s3 = fmaf(qv[j].w, cv[j].w, s3);
        }
        float s = (s0 + s1) + (s2 + s3);
#pragma unroll
        for (int off = 16; off; off >>= 1)
            s += __shfl_xor_sync(0xffffffffu, s, off);

        if (lane == 0)
            g_scores[(size_t)b * NN + split * ROWS_BLK + w * ROWS_W + r] = s;

        // Branchy online softmax (s warp-uniform -> no divergence)
        if (s <= m) {
            const float p = __expf(s - m);
            l += p;
#pragma unroll
            for (int j = 0; j < 8; j++) {
                acc[4 * j + 0] = fmaf(p, cv[j].x, acc[4 * j + 0]);
                acc[4 * j + 1] = fmaf(p, cv[j].y, acc[4 * j + 1]);
                acc[4 * j + 2] = fmaf(p, cv[j].z, acc[4 * j + 2]);
                acc[4 * j + 3] = fmaf(p, cv[j].w, acc[4 * j + 3]);
            }
        } else {
            const float c = __expf(m - s);
            l = fmaf(l, c, 1.f);
#pragma unroll
            for (int j = 0; j < 8; j++) {
                acc[4 * j + 0] = fmaf(acc[4 * j + 0], c, cv[j].x);
                acc[4 * j + 1] = fmaf(acc[4 * j + 1], c, cv[j].y);
                acc[4 * j + 2] = fmaf(acc[4 * j + 2], c, cv[j].z);
                acc[4 * j + 3] = fmaf(acc[4 * j + 3], c, cv[j].w);
            }
            m = s;
        }
    }

    // Drain async groups, then block combine (ring smem reused).
    asm volatile("cp.async.wait_group 0;\n");
    if (lane == 0) { sm[w] = m; sl[w] = l; }
    __syncthreads();

    float M = sm[0];
#pragma unroll
    for (int s2 = 1; s2 < 8; s2++) M = fmaxf(M, sm[s2]);
    float L = 0.f;
#pragma unroll
    for (int s2 = 0; s2 < 8; s2++) L += sl[s2] * __expf(sm[s2] - M);

    const float scale = __expf(m - M);
    float* red = smem;                       // reuse ring region: 8 * DD
#pragma unroll
    for (int j = 0; j < 8; j++) {
        float4 v = make_float4(acc[4 * j + 0] * scale, acc[4 * j + 1] * scale,
                               acc[4 * j + 2] * scale, acc[4 * j + 3] * scale);
        *(float4*)(red + w * DD + j * 128 + lane * 4) = v;
    }
    __syncthreads();

    {
        const int d0 = tid * 4;
        float4 r = *(const float4*)(red + d0);
#pragma unroll
        for (int ww = 1; ww < 8; ww++) {
            float4 v = *(const float4*)(red + ww * DD + d0);
            r.x += v.x; r.y += v.y; r.z += v.z; r.w += v.w;
        }
        const int ps = b * SPLIT + split;
        *(float4*)(&g_part_mix[(size_t)ps * DD + d0]) = r;
        if (tid == 0) { g_part_m[ps] = M; g_part_l[ps] = L; }
    }

    // ---- fused k2: last block per batch does the split combine ----
    __threadfence();
    if (tid == 0)
        is_last = (atomicAdd(&g_ctr_b[b], 1) == SPLIT - 1);
    __syncthreads();
    if (!is_last) return;
    __threadfence();

    float Mg = -1e30f;
#pragma unroll
    for (int s = 0; s < SPLIT; s++) Mg = fmaxf(Mg, g_part_m[b * SPLIT + s]);
    float Lg = 0.f;
#pragma unroll
    for (int s = 0; s < SPLIT; s++)
        Lg += g_part_l[b * SPLIT + s] * __expf(g_part_m[b * SPLIT + s] - Mg);
    const float invL = 1.f / Lg;

    {
        const int d0 = tid * 4;
        float4 r = make_float4(0.f, 0.f, 0.f, 0.f);
#pragma unroll
        for (int s = 0; s < SPLIT; s++) {
            const float wg = __expf(g_part_m[b * SPLIT + s] - Mg);
            float4 v = *(const float4*)
                (&g_part_mix[(size_t)(b * SPLIT + s) * DD + d0]);
            r.x = fmaf(v.x, wg, r.x);
            r.y = fmaf(v.y, wg, r.y);
            r.z = fmaf(v.z, wg, r.z);
            r.w = fmaf(v.w, wg, r.w);
        }
        r.x *= invL; r.y *= invL; r.z *= invL; r.w *= invL;
        *(float4*)(&g_comb[(size_t)b * 2 * DD + d0]) = r;
        *(float4*)(&g_comb[(size_t)b * 2 * DD + DD + d0]) =
            *(const float4*)(output + (size_t)b * DD + d0);
    }
#pragma unroll
    for (int i = 0; i < 8; i++) {
        const int n = tid + i * 256;
        attn_out[(size_t)b * NN + n] =
            __expf(g_scores[(size_t)b * NN + n] - Mg) * invL;
    }
    __syncthreads();
    if (tid == 0) g_ctr_b[b] = 0;            // reset for next graph replay
}

// ---------------------------------------------------------------------------
// Kernel 3: out_part = comb @ W^T + fused finalize.
// 64d x 64b x 256e per block, grid (16, ESPLIT=8), 256 threads, 4x4 tile.
// Last block per d-tile (counter over es) reduces partials + bias + tanh.
// ---------------------------------------------------------------------------
__global__ __launch_bounds__(256)
void k3_gemm(const float* __restrict__ W,
             const float* __restrict__ bias,
             float* __restrict__ out) {
    const int dt  = blockIdx.x;
    const int es  = blockIdx.y;
    const int tid = threadIdx.x;
    const int d0  = dt * 64;
    const int e0  = es * 256;
    const int dg  = tid & 15;
    const int bg  = tid >> 4;

    __shared__ float Ws[64][33];  // [d][k]
    __shared__ float Cs[64][33];  // [b][k]
    __shared__ int is_last;

    float acc[4][4];
#pragma unroll
    for (int i = 0; i < 4; i++)
#pragma unroll
        for (int j = 0; j < 4; j++) acc[i][j] = 0.f;

    for (int ec = 0; ec < 256; ec += 32) {
#pragma unroll
        for (int i = 0; i < 8; i++) {
            int idx = tid + i * 256;
            int r = idx >> 5, c = idx & 31;
            Ws[r][c] = W[(size_t)(d0 + r) * (2 * DD) + e0 + ec + c];
            Cs[r][c] = g_comb[(size_t)r * (2 * DD) + e0 + ec + c];
        }
        __syncthreads();
#pragma unroll
        for (int k = 0; k < 32; k++) {
            float wv[4], cvv[4];
#pragma unroll
            for (int j = 0; j < 4; j++) wv[j] = Ws[dg + 16 * j][k];
#pragma unroll
            for (int i = 0; i < 4; i++) cvv[i] = Cs[bg + 16 * i][k];
#pragma unroll
            for (int i = 0; i < 4; i++)
#pragma unroll
                for (int j = 0; j < 4; j++)
                    acc[i][j] = fmaf(cvv[i], wv[j], acc[i][j]);
        }
        __syncthreads();
    }

#pragma unroll
    for (int i = 0; i < 4; i++)
#pragma unroll
        for (int j = 0; j < 4; j++) {
            const int bidx = bg + 16 * i;
            const int didx = d0 + dg + 16 * j;
            g_out_part[((size_t)bidx * DD + didx) * ESPLIT + es] = acc[i][j];
        }

    // ---- fused k4: last e-split block finalizes this d-tile ----
    __threadfence();
    if (tid == 0)
        is_last = (atomicAdd(&g_ctr_dt[dt], 1) == ESPLIT - 1);
    __syncthreads();
    if (!is_last) return;
    __threadfence();

    for (int t = tid; t < 64 * 64; t += 256) {
        const int bi = t >> 6;
        const int di = d0 + (t & 63);
        const size_t base = ((size_t)bi * DD + di) * ESPLIT;
        const float4 a  = *(const float4*)(&g_out_part[base]);
        const float4 b4 = *(const float4*)(&g_out_part[base + 4]);
        float v = ((a.x + a.y) + (a.z + a.w)) +
                  ((b4.x + b4.y) + (b4.z + b4.w)) + bias[di];
        float r;
        asm("tanh.approx.f32 %0, %1;" : "=f"(r) : "f"(v));
        out[(size_t)bi * DD + di] = r;
    }
    __syncthreads();
    if (tid == 0) g_ctr_dt[dt] = 0;          // reset for next graph replay
}

// ---------------------------------------------------------------------------
extern "C" void kernel_launch(void* const* d_in, const int* in_sizes, int n_in,
                              void* d_out, int out_size) {
    const float* output  = (const float*)d_in[0];  // (64,1,1024)
    const float* context = (const float*)d_in[1];  // (64,2048,1024)
    const float* W_out   = (const float*)d_in[2];  // (1024,2048)
    const float* b_out   = (const float*)d_in[3];  // (1024)

    float* out  = (float*)d_out;       // (64,1,1024) first
    float* attn = out + BB * DD;       // (64,1,2048) second

    static int smem_set = 0;
    if (!smem_set) {
        cudaFuncSetAttribute(k1_scores_mix,
                             cudaFuncAttributeMaxDynamicSharedMemorySize,
                             SMEM_K1);
        smem_set = 1;
    }

    k1_scores_mix<<<dim3(SPLIT, BB), 256, SMEM_K1>>>(output, context, attn);
    k3_gemm<<<dim3(16, ESPLIT), 256>>>(W_out, b_out, out);
}

// round 10
// speedup vs baseline: 1.1987x; 1.1987x over previous
#include <cuda_runtime.h>
#include <cuda_bf16.h>

#define BB 64
#define NN 2048
#define DD 1024
#define SPLIT 32
#define ROWS_BLK (NN / SPLIT)   // 64 rows per block
#define ROWS_W 8                // rows per warp
#define SBUF 3                  // per-warp ring depth
#define ESPLIT 16

#define SMEM_K1 (8 * SBUF * DD * 4)   // 8 warps * 3 slots * 4KB = 98304 B

// Scratch (static device globals; no allocation)
__device__ float g_scores[BB * NN];
__device__ float g_part_m[BB * SPLIT];
__device__ float g_part_l[BB * SPLIT];
__device__ float g_part_mix[BB * SPLIT * DD];    // 8 MB
__device__ float g_comb[BB * 2 * DD];            // [mix | output]
__device__ float g_out_part[BB * DD * ESPLIT];   // es-contiguous, 4 MB

__device__ __forceinline__ unsigned smem_u32(const void* p) {
    return (unsigned)__cvta_generic_to_shared(p);
}

// One 4KB row: lane i copies 16B chunks i, 32+i, ... (self-consistent:
// each lane later reads exactly the chunks it issued).
__device__ __forceinline__ void issue_row(float* dst, const float* src,
                                          int lane) {
#pragma unroll
    for (int c = 0; c < 8; c++) {
        const int f = (c * 32 + lane) * 4;   // float index
        unsigned sa = smem_u32(dst + f);
        asm volatile("cp.async.cg.shared.global [%0], [%1], 16;\n"
                     :: "r"(sa), "l"(src + f));
    }
}

// ---------------------------------------------------------------------------
// Kernel 1: barrier-free per-warp cp.async pipelines (R3/R6-proven, verbatim).
// ---------------------------------------------------------------------------
__global__ __launch_bounds__(256, 2)
void k1_scores_mix(const float* __restrict__ output,
                   const float* __restrict__ context) {
    extern __shared__ float smem[];          // 8 * SBUF * DD floats
    __shared__ float sm[8], sl[8];

    const int split = blockIdx.x;
    const int b     = blockIdx.y;
    const int tid   = threadIdx.x;
    const int w     = tid >> 5;
    const int lane  = tid & 31;

    const float* q   = output + (size_t)b * DD;
    const float* ctx = context + (size_t)b * NN * DD
                               + (size_t)(split * ROWS_BLK + w * ROWS_W) * DD;
    float* ring = smem + w * (SBUF * DD);

    float4 qv[8];
#pragma unroll
    for (int j = 0; j < 8; j++)
        qv[j] = *(const float4*)(q + j * 128 + lane * 4);

    float acc[32];
#pragma unroll
    for (int k = 0; k < 32; k++) acc[k] = 0.f;
    float m = -1e30f, l = 0.f;

#pragma unroll
    for (int ps = 0; ps < SBUF - 1; ps++) {
        issue_row(ring + ps * DD, ctx + (size_t)ps * DD, lane);
        asm volatile("cp.async.commit_group;\n");
    }

#pragma unroll
    for (int r = 0; r < ROWS_W; r++) {
        asm volatile("cp.async.wait_group 1;\n");
        __syncwarp();

        if (r + SBUF - 1 < ROWS_W)
            issue_row(ring + ((r + SBUF - 1) % SBUF) * DD,
                      ctx + (size_t)(r + SBUF - 1) * DD, lane);
        asm volatile("cp.async.commit_group;\n");

        const float* row = ring + (r % SBUF) * DD;
        float4 cv[8];
#pragma unroll
        for (int j = 0; j < 8; j++)
            cv[j] = *(const float4*)(row + j * 128 + lane * 4);

        float s0 = 0.f, s1 = 0.f, s2 = 0.f, s3 = 0.f;
#pragma unroll
        for (int j = 0; j < 8; j++) {
            s0 = fmaf(qv[j].x, cv[j].x, s0);
            s1 = fmaf(qv[j].y, cv[j].y, s1);
            s2 = fmaf(qv[j].z, cv[j].z, s2);
            s3 = fmaf(qv[j].w, cv[j].w, s3);
        }
        float s = (s0 + s1) + (s2 + s3);
#pragma unroll
        for (int off = 16; off; off >>= 1)
            s += __shfl_xor_sync(0xffffffffu, s, off);

        if (lane == 0)
            g_scores[(size_t)b * NN + split * ROWS_BLK + w * ROWS_W + r] = s;

        if (s <= m) {
            const float p = __expf(s - m);
            l += p;
#pragma unroll
            for (int j = 0; j < 8; j++) {
                acc[4 * j + 0] = fmaf(p, cv[j].x, acc[4 * j + 0]);
                acc[4 * j + 1] = fmaf(p, cv[j].y, acc[4 * j + 1]);
                acc[4 * j + 2] = fmaf(p, cv[j].z, acc[4 * j + 2]);
                acc[4 * j + 3] = fmaf(p, cv[j].w, acc[4 * j + 3]);
            }
        } else {
            const float c = __expf(m - s);
            l = fmaf(l, c, 1.f);
#pragma unroll
            for (int j = 0; j < 8; j++) {
                acc[4 * j + 0] = fmaf(acc[4 * j + 0], c, cv[j].x);
                acc[4 * j + 1] = fmaf(acc[4 * j + 1], c, cv[j].y);
                acc[4 * j + 2] = fmaf(acc[4 * j + 2], c, cv[j].z);
                acc[4 * j + 3] = fmaf(acc[4 * j + 3], c, cv[j].w);
            }
            m = s;
        }
    }

    asm volatile("cp.async.wait_group 0;\n");
    if (lane == 0) { sm[w] = m; sl[w] = l; }
    __syncthreads();

    float M = sm[0];
#pragma unroll
    for (int s2 = 1; s2 < 8; s2++) M = fmaxf(M, sm[s2]);
    float L = 0.f;
#pragma unroll
    for (int s2 = 0; s2 < 8; s2++) L += sl[s2] * __expf(sm[s2] - M);

    const float scale = __expf(m - M);
    float* red = smem;
#pragma unroll
    for (int j = 0; j < 8; j++) {
        float4 v = make_float4(acc[4 * j + 0] * scale, acc[4 * j + 1] * scale,
                               acc[4 * j + 2] * scale, acc[4 * j + 3] * scale);
        *(float4*)(red + w * DD + j * 128 + lane * 4) = v;
    }
    __syncthreads();

    {
        const int d0 = tid * 4;
        float4 r = *(const float4*)(red + d0);
#pragma unroll
        for (int ww = 1; ww < 8; ww++) {
            float4 v = *(const float4*)(red + ww * DD + d0);
            r.x += v.x; r.y += v.y; r.z += v.z; r.w += v.w;
        }
        const int ps = b * SPLIT + split;
        *(float4*)(&g_part_mix[(size_t)ps * DD + d0]) = r;
        if (tid == 0) { g_part_m[ps] = M; g_part_l[ps] = L; }
    }
}

// ---------------------------------------------------------------------------
// Kernel 2: combine splits. grid (BB, 2): y=0 mix+comb, y=1 attn+copy.
// ---------------------------------------------------------------------------
__global__ __launch_bounds__(256)
void k2_combine(const float* __restrict__ output,
                float* __restrict__ attn_out) {
    const int b   = blockIdx.x;
    const int tid = threadIdx.x;

    float M = -1e30f;
#pragma unroll
    for (int s = 0; s < SPLIT; s++) M = fmaxf(M, g_part_m[b * SPLIT + s]);
    float L = 0.f;
#pragma unroll
    for (int s = 0; s < SPLIT; s++)
        L += g_part_l[b * SPLIT + s] * __expf(g_part_m[b * SPLIT + s] - M);
    const float invL = 1.f / L;

    if (blockIdx.y == 0) {
        const int d0 = tid * 4;
        float4 r = make_float4(0.f, 0.f, 0.f, 0.f);
#pragma unroll
        for (int s = 0; s < SPLIT; s++) {
            const float wg = __expf(g_part_m[b * SPLIT + s] - M);
            float4 v = *(const float4*)
                (&g_part_mix[(size_t)(b * SPLIT + s) * DD + d0]);
            r.x = fmaf(v.x, wg, r.x);
            r.y = fmaf(v.y, wg, r.y);
            r.z = fmaf(v.z, wg, r.z);
            r.w = fmaf(v.w, wg, r.w);
        }
        r.x *= invL; r.y *= invL; r.z *= invL; r.w *= invL;
        *(float4*)(&g_comb[(size_t)b * 2 * DD + d0]) = r;
    } else {
#pragma unroll
        for (int i = 0; i < 8; i++) {
            const int n = tid + i * 256;
            attn_out[(size_t)b * NN + n] =
                __expf(g_scores[(size_t)b * NN + n] - M) * invL;
        }
        const int d0 = tid * 4;
        *(float4*)(&g_comb[(size_t)b * 2 * DD + DD + d0]) =
            *(const float4*)(output + (size_t)b * DD + d0);
    }
}

// ---------------------------------------------------------------------------
// Kernel 3: out_part = comb @ W^T. 64d x 64b x 128e per block,
// grid (16, ESPLIT=16) = 256 blocks (2 CTAs/SM), 256 threads, 4x4 reg tile,
// REGISTER DOUBLE-BUFFERED fragments to hide the 29-cyc LDS latency.
// ---------------------------------------------------------------------------
__global__ __launch_bounds__(256, 2)
void k3_gemm(const float* __restrict__ W) {
    const int dt  = blockIdx.x;
    const int es  = blockIdx.y;
    const int tid = threadIdx.x;
    const int d0  = dt * 64;
    const int e0  = es * 128;
    const int dg  = tid & 15;
    const int bg  = tid >> 4;

    __shared__ float Ws[64][33];  // [d][k]
    __shared__ float Cs[64][33];  // [b][k]

    float acc[4][4];
#pragma unroll
    for (int i = 0; i < 4; i++)
#pragma unroll
        for (int j = 0; j < 4; j++) acc[i][j] = 0.f;

    for (int ec = 0; ec < 128; ec += 32) {
#pragma unroll
        for (int i = 0; i < 8; i++) {
            int idx = tid + i * 256;
            int r = idx >> 5, c = idx & 31;
            Ws[r][c] = W[(size_t)(d0 + r) * (2 * DD) + e0 + ec + c];
            Cs[r][c] = g_comb[(size_t)r * (2 * DD) + e0 + ec + c];
        }
        __syncthreads();

        float wv[2][4], cvv[2][4];
#pragma unroll
        for (int j = 0; j < 4; j++) {
            wv[0][j]  = Ws[dg + 16 * j][0];
            cvv[0][j] = Cs[bg + 16 * j][0];
        }
#pragma unroll
        for (int k = 0; k < 32; k++) {
            const int cur = k & 1, nxt = cur ^ 1;
            if (k < 31) {
#pragma unroll
                for (int j = 0; j < 4; j++) {
                    wv[nxt][j]  = Ws[dg + 16 * j][k + 1];
                    cvv[nxt][j] = Cs[bg + 16 * j][k + 1];
                }
            }
#pragma unroll
            for (int i = 0; i < 4; i++)
#pragma unroll
                for (int j = 0; j < 4; j++)
                    acc[i][j] = fmaf(cvv[cur][i], wv[cur][j], acc[i][j]);
        }
        __syncthreads();
    }

#pragma unroll
    for (int i = 0; i < 4; i++)
#pragma unroll
        for (int j = 0; j < 4; j++) {
            const int bidx = bg + 16 * i;
            const int didx = d0 + dg + 16 * j;
            g_out_part[((size_t)bidx * DD + didx) * ESPLIT + es] = acc[i][j];
        }
}

// ---------------------------------------------------------------------------
// Kernel 4: es-contiguous partial reduce (16) + bias + tanh.
// ---------------------------------------------------------------------------
__global__ void k4_final(const float* __restrict__ bias,
                         float* __restrict__ out) {
    const int idx = blockIdx.x * blockDim.x + threadIdx.x;  // 0..65535
    const int d = idx & (DD - 1);
    const size_t base = (size_t)idx * ESPLIT;
    float v = bias[d];
#pragma unroll
    for (int g = 0; g < ESPLIT; g += 4) {
        const float4 a = *(const float4*)(&g_out_part[base + g]);
        v += (a.x + a.y) + (a.z + a.w);
    }
    float r;
    asm("tanh.approx.f32 %0, %1;" : "=f"(r) : "f"(v));
    out[idx] = r;
}

// ---------------------------------------------------------------------------
extern "C" void kernel_launch(void* const* d_in, const int* in_sizes, int n_in,
                              void* d_out, int out_size) {
    const float* output  = (const float*)d_in[0];  // (64,1,1024)
    const float* context = (const float*)d_in[1];  // (64,2048,1024)
    const float* W_out   = (const float*)d_in[2];  // (1024,2048)
    const float* b_out   = (const float*)d_in[3];  // (1024)

    float* out  = (float*)d_out;       // (64,1,1024) first
    float* attn = out + BB * DD;       // (64,1,2048) second

    static int smem_set = 0;
    if (!smem_set) {
        cudaFuncSetAttribute(k1_scores_mix,
                             cudaFuncAttributeMaxDynamicSharedMemorySize,
                             SMEM_K1);
        smem_set = 1;
    }

    k1_scores_mix<<<dim3(SPLIT, BB), 256, SMEM_K1>>>(output, context);
    k2_combine<<<dim3(BB, 2), 256>>>(output, attn);
    k3_gemm<<<dim3(16, ESPLIT), 256>>>(W_out);
    k4_final<<<256, 256>>>(b_out, out);
}

// round 14
// speedup vs baseline: 1.2137x; 1.0125x over previous
#include <cuda_runtime.h>
#include <cuda_bf16.h>

#define BB 64
#define NN 2048
#define DD 1024
#define SPLIT 32
#define ROWS_BLK (NN / SPLIT)   // 64 rows per block
#define ROWS_W 8                // rows per warp
#define SBUF 3                  // per-warp ring depth
#define ESPLIT 16

#define SMEM_K1 (8 * SBUF * DD * 4)   // 8 warps * 3 slots * 4KB = 98304 B

// Scratch (static device globals; no allocation)
__device__ float g_scores[BB * NN];
__device__ float g_part_m[BB * SPLIT];
__device__ float g_part_l[BB * SPLIT];
__device__ float g_part_mix[BB * SPLIT * DD];    // 8 MB
__device__ float g_comb[BB * 2 * DD];            // [mix | output]
__device__ float g_out_part[BB * DD * ESPLIT];   // es-contiguous, 4 MB

__device__ __forceinline__ unsigned smem_u32(const void* p) {
    return (unsigned)__cvta_generic_to_shared(p);
}

// One 4KB row: lane i copies 16B chunks i, 32+i, ... (self-consistent:
// each lane later reads exactly the chunks it issued).
__device__ __forceinline__ void issue_row(float* dst, const float* src,
                                          int lane) {
#pragma unroll
    for (int c = 0; c < 8; c++) {
        const int f = (c * 32 + lane) * 4;   // float index
        unsigned sa = smem_u32(dst + f);
        asm volatile("cp.async.cg.shared.global [%0], [%1], 16;\n"
                     :: "r"(sa), "l"(src + f));
    }
}

// ---------------------------------------------------------------------------
// Kernel 1: barrier-free per-warp cp.async pipelines (R3/R6-proven, frozen).
// ---------------------------------------------------------------------------
__global__ __launch_bounds__(256, 2)
void k1_scores_mix(const float* __restrict__ output,
                   const float* __restrict__ context) {
    extern __shared__ float smem[];          // 8 * SBUF * DD floats
    __shared__ float sm[8], sl[8];

    const int split = blockIdx.x;
    const int b     = blockIdx.y;
    const int tid   = threadIdx.x;
    const int w     = tid >> 5;
    const int lane  = tid & 31;

    const float* q   = output + (size_t)b * DD;
    const float* ctx = context + (size_t)b * NN * DD
                               + (size_t)(split * ROWS_BLK + w * ROWS_W) * DD;
    float* ring = smem + w * (SBUF * DD);

    float4 qv[8];
#pragma unroll
    for (int j = 0; j < 8; j++)
        qv[j] = *(const float4*)(q + j * 128 + lane * 4);

    float acc[32];
#pragma unroll
    for (int k = 0; k < 32; k++) acc[k] = 0.f;
    float m = -1e30f, l = 0.f;

#pragma unroll
    for (int ps = 0; ps < SBUF - 1; ps++) {
        issue_row(ring + ps * DD, ctx + (size_t)ps * DD, lane);
        asm volatile("cp.async.commit_group;\n");
    }

#pragma unroll
    for (int r = 0; r < ROWS_W; r++) {
        asm volatile("cp.async.wait_group 1;\n");
        __syncwarp();

        if (r + SBUF - 1 < ROWS_W)
            issue_row(ring + ((r + SBUF - 1) % SBUF) * DD,
                      ctx + (size_t)(r + SBUF - 1) * DD, lane);
        asm volatile("cp.async.commit_group;\n");

        const float* row = ring + (r % SBUF) * DD;
        float4 cv[8];
#pragma unroll
        for (int j = 0; j < 8; j++)
            cv[j] = *(const float4*)(row + j * 128 + lane * 4);

        float s0 = 0.f, s1 = 0.f, s2 = 0.f, s3 = 0.f;
#pragma unroll
        for (int j = 0; j < 8; j++) {
            s0 = fmaf(qv[j].x, cv[j].x, s0);
            s1 = fmaf(qv[j].y, cv[j].y, s1);
            s2 = fmaf(qv[j].z, cv[j].z, s2);
            s3 = fmaf(qv[j].w, cv[j].w, s3);
        }
        float s = (s0 + s1) + (s2 + s3);
#pragma unroll
        for (int off = 16; off; off >>= 1)
            s += __shfl_xor_sync(0xffffffffu, s, off);

        if (lane == 0)
            g_scores[(size_t)b * NN + split * ROWS_BLK + w * ROWS_W + r] = s;

        if (s <= m) {
            const float p = __expf(s - m);
            l += p;
#pragma unroll
            for (int j = 0; j < 8; j++) {
                acc[4 * j + 0] = fmaf(p, cv[j].x, acc[4 * j + 0]);
                acc[4 * j + 1] = fmaf(p, cv[j].y, acc[4 * j + 1]);
                acc[4 * j + 2] = fmaf(p, cv[j].z, acc[4 * j + 2]);
                acc[4 * j + 3] = fmaf(p, cv[j].w, acc[4 * j + 3]);
            }
        } else {
            const float c = __expf(m - s);
            l = fmaf(l, c, 1.f);
#pragma unroll
            for (int j = 0; j < 8; j++) {
                acc[4 * j + 0] = fmaf(acc[4 * j + 0], c, cv[j].x);
                acc[4 * j + 1] = fmaf(acc[4 * j + 1], c, cv[j].y);
                acc[4 * j + 2] = fmaf(acc[4 * j + 2], c, cv[j].z);
                acc[4 * j + 3] = fmaf(acc[4 * j + 3], c, cv[j].w);
            }
            m = s;
        }
    }

    asm volatile("cp.async.wait_group 0;\n");
    if (lane == 0) { sm[w] = m; sl[w] = l; }
    __syncthreads();

    float M = sm[0];
#pragma unroll
    for (int s2 = 1; s2 < 8; s2++) M = fmaxf(M, sm[s2]);
    float L = 0.f;
#pragma unroll
    for (int s2 = 0; s2 < 8; s2++) L += sl[s2] * __expf(sm[s2] - M);

    const float scale = __expf(m - M);
    float* red = smem;
#pragma unroll
    for (int j = 0; j < 8; j++) {
        float4 v = make_float4(acc[4 * j + 0] * scale, acc[4 * j + 1] * scale,
                               acc[4 * j + 2] * scale, acc[4 * j + 3] * scale);
        *(float4*)(red + w * DD + j * 128 + lane * 4) = v;
    }
    __syncthreads();

    {
        const int d0 = tid * 4;
        float4 r = *(const float4*)(red + d0);
#pragma unroll
        for (int ww = 1; ww < 8; ww++) {
            float4 v = *(const float4*)(red + ww * DD + d0);
            r.x += v.x; r.y += v.y; r.z += v.z; r.w += v.w;
        }
        const int ps = b * SPLIT + split;
        *(float4*)(&g_part_mix[(size_t)ps * DD + d0]) = r;
        if (tid == 0) { g_part_m[ps] = M; g_part_l[ps] = L; }
    }
}

// ---------------------------------------------------------------------------
// Kernel 2: combine splits. grid (BB, 2): y=0 mix+comb, y=1 attn+copy.
// ---------------------------------------------------------------------------
__global__ __launch_bounds__(256)
void k2_combine(const float* __restrict__ output,
                float* __restrict__ attn_out) {
    const int b   = blockIdx.x;
    const int tid = threadIdx.x;

    float M = -1e30f;
#pragma unroll
    for (int s = 0; s < SPLIT; s++) M = fmaxf(M, g_part_m[b * SPLIT + s]);
    float L = 0.f;
#pragma unroll
    for (int s = 0; s < SPLIT; s++)
        L += g_part_l[b * SPLIT + s] * __expf(g_part_m[b * SPLIT + s] - M);
    const float invL = 1.f / L;

    if (blockIdx.y == 0) {
        const int d0 = tid * 4;
        float4 r = make_float4(0.f, 0.f, 0.f, 0.f);
#pragma unroll
        for (int s = 0; s < SPLIT; s++) {
            const float wg = __expf(g_part_m[b * SPLIT + s] - M);
            float4 v = *(const float4*)
                (&g_part_mix[(size_t)(b * SPLIT + s) * DD + d0]);
            r.x = fmaf(v.x, wg, r.x);
            r.y = fmaf(v.y, wg, r.y);
            r.z = fmaf(v.z, wg, r.z);
            r.w = fmaf(v.w, wg, r.w);
        }
        r.x *= invL; r.y *= invL; r.z *= invL; r.w *= invL;
        *(float4*)(&g_comb[(size_t)b * 2 * DD + d0]) = r;
    } else {
#pragma unroll
        for (int i = 0; i < 8; i++) {
            const int n = tid + i * 256;
            attn_out[(size_t)b * NN + n] =
                __expf(g_scores[(size_t)b * NN + n] - M) * invL;
        }
        const int d0 = tid * 4;
        *(float4*)(&g_comb[(size_t)b * 2 * DD + DD + d0]) =
            *(const float4*)(output + (size_t)b * DD + d0);
    }
}

// ---------------------------------------------------------------------------
// Kernel 3: out_part = comb @ W^T. Block tile 128d x 64b x 128e,
// grid (8, ESPLIT=16) = 128 blocks (one full wave), 256 threads,
// 8x4 (d x b) per-thread tile, register double-buffered fragments.
// Per k-step: 12 LDS + 32 FFMA (1.375 instr/MAC).
// ---------------------------------------------------------------------------
__global__ __launch_bounds__(256, 1)
void k3_gemm(const float* __restrict__ W) {
    const int dt  = blockIdx.x;       // 8 tiles of 128 d
    const int es  = blockIdx.y;       // 16 splits of 128 e
    const int tid = threadIdx.x;
    const int d0  = dt * 128;
    const int e0  = es * 128;
    const int dg  = tid & 15;         // d group: rows dg + 16*j, j=0..7
    const int bg  = tid >> 4;         // b group: rows bg + 16*i, i=0..3

    __shared__ float Ws[128][33];  // [d][k]
    __shared__ float Cs[64][33];   // [b][k]

    float acc[8][4];
#pragma unroll
    for (int j = 0; j < 8; j++)
#pragma unroll
        for (int i = 0; i < 4; i++) acc[j][i] = 0.f;

    for (int ec = 0; ec < 128; ec += 32) {
#pragma unroll
        for (int i = 0; i < 16; i++) {
            int idx = tid + i * 256;
            int r = idx >> 5, c = idx & 31;
            Ws[r][c] = W[(size_t)(d0 + r) * (2 * DD) + e0 + ec + c];
        }
#pragma unroll
        for (int i = 0; i < 8; i++) {
            int idx = tid + i * 256;
            int r = idx >> 5, c = idx & 31;
            Cs[r][c] = g_comb[(size_t)r * (2 * DD) + e0 + ec + c];
        }
        __syncthreads();

        float wv[2][8], cv[2][4];
#pragma unroll
        for (int j = 0; j < 8; j++) wv[0][j] = Ws[dg + 16 * j][0];
#pragma unroll
        for (int i = 0; i < 4; i++) cv[0][i] = Cs[bg + 16 * i][0];

#pragma unroll
        for (int k = 0; k < 32; k++) {
            const int cur = k & 1, nxt = cur ^ 1;
            if (k < 31) {
#pragma unroll
                for (int j = 0; j < 8; j++)
                    wv[nxt][j] = Ws[dg + 16 * j][k + 1];
#pragma unroll
                for (int i = 0; i < 4; i++)
                    cv[nxt][i] = Cs[bg + 16 * i][k + 1];
            }
#pragma unroll
            for (int j = 0; j < 8; j++)
#pragma unroll
                for (int i = 0; i < 4; i++)
                    acc[j][i] = fmaf(cv[cur][i], wv[cur][j], acc[j][i]);
        }
        __syncthreads();
    }

#pragma unroll
    for (int j = 0; j < 8; j++)
#pragma unroll
        for (int i = 0; i < 4; i++) {
            const int bidx = bg + 16 * i;
            const int didx = d0 + dg + 16 * j;
            g_out_part[((size_t)bidx * DD + didx) * ESPLIT + es] = acc[j][i];
        }
}

// ---------------------------------------------------------------------------
// Kernel 4: es-contiguous partial reduce (16) + bias + tanh.
// ---------------------------------------------------------------------------
__global__ void k4_final(const float* __restrict__ bias,
                         float* __restrict__ out) {
    const int idx = blockIdx.x * blockDim.x + threadIdx.x;  // 0..65535
    const int d = idx & (DD - 1);
    const size_t base = (size_t)idx * ESPLIT;
    float v = bias[d];
#pragma unroll
    for (int g = 0; g < ESPLIT; g += 4) {
        const float4 a = *(const float4*)(&g_out_part[base + g]);
        v += (a.x + a.y) + (a.z + a.w);
    }
    float r;
    asm("tanh.approx.f32 %0, %1;" : "=f"(r) : "f"(v));
    out[idx] = r;
}

// ---------------------------------------------------------------------------
extern "C" void kernel_launch(void* const* d_in, const int* in_sizes, int n_in,
                              void* d_out, int out_size) {
    const float* output  = (const float*)d_in[0];  // (64,1,1024)
    const float* context = (const float*)d_in[1];  // (64,2048,1024)
    const float* W_out   = (const float*)d_in[2];  // (1024,2048)
    const float* b_out   = (const float*)d_in[3];  // (1024)

    float* out  = (float*)d_out;       // (64,1,1024) first
    float* attn = out + BB * DD;       // (64,1,2048) second

    static int smem_set = 0;
    if (!smem_set) {
        cudaFuncSetAttribute(k1_scores_mix,
                             cudaFuncAttributeMaxDynamicSharedMemorySize,
                             SMEM_K1);
        smem_set = 1;
    }

    k1_scores_mix<<<dim3(SPLIT, BB), 256, SMEM_K1>>>(output, context);
    k2_combine<<<dim3(BB, 2), 256>>>(output, attn);
    k3_gemm<<<dim3(8, ESPLIT), 256>>>(W_out);
    k4_final<<<256, 256>>>(b_out, out);
}